// round 5
// baseline (speedup 1.0000x reference)
#include <cuda_runtime.h>

#define NN 512          // nodes
#define C1 36
#define C2 24
#define C3 8
#define EMAX (NN * NN)

// ---- scratch (device globals; no allocs allowed) ----
__device__ __align__(16) float g_agg1[NN * C1];
__device__ __align__(16) float g_agg2[NN * C2];
__device__ __align__(16) float g_agg3[NN * C3];
__device__ __align__(16) float g_h1[NN * C1];
__device__ __align__(16) float g_h2[NN * C2];
__device__ __align__(16) float g_h3[NN * C3];
__device__ int g_cnt[NN];
__device__ int g_src[EMAX];
__device__ int g_dst[EMAX];
__device__ int g_is64;

// ---------------- dtype detection: int64 vs int32 edge_index ----------------
// Reference declares jnp.int64, but JAX with x64 disabled silently emits int32.
// If the first 64 values read as int64 are all in [0, NN), it's real int64
// (false-positive prob with int32 data ~ (1/512)^64 ~ 0). Else int32.
__global__ void k_detect(const long long* __restrict__ ei) {
    if (threadIdx.x == 0) {
        int ok = 1;
        for (int i = 0; i < 64; i++) {
            long long v = ei[i];
            if (v < 0 || v >= NN) { ok = 0; break; }
        }
        g_is64 = ok;
    }
}

// ---------------- convert indices to clean int32, hard-clamped ----------------
__global__ void k_convert(const void* __restrict__ ei, int E) {
    int e = blockIdx.x * blockDim.x + threadIdx.x;
    if (e >= E) return;
    int s, d;
    if (g_is64) {
        const long long* p = (const long long*)ei;
        s = (int)p[e]; d = (int)p[E + e];
    } else {
        const int* p = (const int*)ei;
        s = p[e]; d = p[E + e];
    }
    g_src[e] = s & (NN - 1);   // guarantees in-bounds no matter what
    g_dst[e] = d & (NN - 1);
}

// ---------------- zero scratch + dst histogram ----------------
__global__ void k_zero() {
    int i = blockIdx.x * blockDim.x + threadIdx.x;
    if (i < NN * C1) g_agg1[i] = 0.f;
    if (i < NN * C2) g_agg2[i] = 0.f;
    if (i < NN * C3) g_agg3[i] = 0.f;
    if (i < NN)      g_cnt[i] = 0;
}

__global__ void k_hist(int E) {
    __shared__ int s[NN];
    for (int i = threadIdx.x; i < NN; i += blockDim.x) s[i] = 0;
    __syncthreads();
    for (int e = blockIdx.x * blockDim.x + threadIdx.x; e < E; e += gridDim.x * blockDim.x)
        atomicAdd(&s[g_dst[e]], 1);
    __syncthreads();
    for (int i = threadIdx.x; i < NN; i += blockDim.x)
        if (s[i]) atomicAdd(&g_cnt[i], s[i]);
}

// ---------------- layer 1 edge: cin=1, cout=36 ----------------
__global__ __launch_bounds__(256) void k_edge1(
    const float* __restrict__ x, const float4* __restrict__ ea,
    const float* __restrict__ W, const float* __restrict__ b, int E)
{
    __shared__ float4 Ws[C1];
    __shared__ float bs[C1];
    int t = threadIdx.x;
    if (t < C1) {
        Ws[t] = make_float4(W[t], W[C1 + t], W[2 * C1 + t], W[3 * C1 + t]);
        bs[t] = b[t];
    }
    __syncthreads();
    int e = blockIdx.x * blockDim.x + t;
    if (e >= E) return;
    float4 a = ea[e];
    int src = g_src[e], dst = g_dst[e];
    float xi = __ldg(x + src);
    float* p = g_agg1 + dst * C1;
#pragma unroll
    for (int o = 0; o < C1; o++) {
        float4 w = Ws[o];
        float v = fmaf(a.x, w.x, fmaf(a.y, w.y, fmaf(a.z, w.z, fmaf(a.w, w.w, bs[o]))));
        atomicAdd(p + o, xi * fmaxf(v, 0.f));
    }
}

// ---------------- layer 2 edge: cin=36, cout=24 ----------------
__global__ __launch_bounds__(256) void k_edge2(
    const float4* __restrict__ ea,
    const float* __restrict__ W, const float* __restrict__ b, int E)
{
    __shared__ float4 Ws[C1 * C2];   // 13824 B
    __shared__ float bs[C1 * C2];    //  3456 B
    int t = threadIdx.x;
    for (int io = t; io < C1 * C2; io += blockDim.x) {
        Ws[io] = make_float4(W[io], W[864 + io], W[1728 + io], W[2592 + io]);
        bs[io] = b[io];
    }
    __syncthreads();
    int e = blockIdx.x * blockDim.x + t;
    if (e >= E) return;
    float4 a = ea[e];
    int src = g_src[e], dst = g_dst[e];
    float h[C1];
    const float4* hp = (const float4*)(g_h1 + src * C1);
#pragma unroll
    for (int q = 0; q < C1 / 4; q++) {
        float4 v = __ldg(hp + q);
        h[4 * q] = v.x; h[4 * q + 1] = v.y; h[4 * q + 2] = v.z; h[4 * q + 3] = v.w;
    }
    float acc[C2];
#pragma unroll
    for (int o = 0; o < C2; o++) acc[o] = 0.f;
#pragma unroll 4
    for (int i = 0; i < C1; i++) {
        float xi = h[i];
        const float4* wrow = Ws + i * C2;
        const float* brow = bs + i * C2;
#pragma unroll
        for (int o = 0; o < C2; o++) {
            float4 w = wrow[o];
            float v = fmaf(a.x, w.x, fmaf(a.y, w.y, fmaf(a.z, w.z, fmaf(a.w, w.w, brow[o]))));
            acc[o] = fmaf(xi, fmaxf(v, 0.f), acc[o]);
        }
    }
    float* p = g_agg2 + dst * C2;
#pragma unroll
    for (int o = 0; o < C2; o++) atomicAdd(p + o, acc[o]);
}

// ---------------- layer 3 edge: cin=24, cout=8 ----------------
__global__ __launch_bounds__(256) void k_edge3(
    const float4* __restrict__ ea,
    const float* __restrict__ W, const float* __restrict__ b, int E)
{
    __shared__ float4 Ws[C2 * C3];   // 3072 B
    __shared__ float bs[C2 * C3];
    int t = threadIdx.x;
    for (int io = t; io < C2 * C3; io += blockDim.x) {
        Ws[io] = make_float4(W[io], W[192 + io], W[384 + io], W[576 + io]);
        bs[io] = b[io];
    }
    __syncthreads();
    int e = blockIdx.x * blockDim.x + t;
    if (e >= E) return;
    float4 a = ea[e];
    int src = g_src[e], dst = g_dst[e];
    float h[C2];
    const float4* hp = (const float4*)(g_h2 + src * C2);
#pragma unroll
    for (int q = 0; q < C2 / 4; q++) {
        float4 v = __ldg(hp + q);
        h[4 * q] = v.x; h[4 * q + 1] = v.y; h[4 * q + 2] = v.z; h[4 * q + 3] = v.w;
    }
    float acc[C3];
#pragma unroll
    for (int o = 0; o < C3; o++) acc[o] = 0.f;
#pragma unroll
    for (int i = 0; i < C2; i++) {
        float xi = h[i];
        const float4* wrow = Ws + i * C3;
        const float* brow = bs + i * C3;
#pragma unroll
        for (int o = 0; o < C3; o++) {
            float4 w = wrow[o];
            float v = fmaf(a.x, w.x, fmaf(a.y, w.y, fmaf(a.z, w.z, fmaf(a.w, w.w, brow[o]))));
            acc[o] = fmaf(xi, fmaxf(v, 0.f), acc[o]);
        }
    }
    float* p = g_agg3 + dst * C3;
#pragma unroll
    for (int o = 0; o < C3; o++) atomicAdd(p + o, acc[o]);
}

// ---------------- node kernels: h = relu(agg/cnt + hprev@root + bias) ----------------
__global__ void k_node1(const float* __restrict__ x, const float* __restrict__ root,
                        const float* __restrict__ bias) {
    int idx = blockIdx.x * blockDim.x + threadIdx.x;
    if (idx >= NN * C1) return;
    int n = idx / C1, o = idx % C1;
    float c = (float)max(g_cnt[n], 1);
    float v = g_agg1[idx] / c + bias[o] + x[n] * root[o];
    g_h1[idx] = fmaxf(v, 0.f);
}
__global__ void k_node2(const float* __restrict__ root, const float* __restrict__ bias) {
    int idx = blockIdx.x * blockDim.x + threadIdx.x;
    if (idx >= NN * C2) return;
    int n = idx / C2, o = idx % C2;
    float c = (float)max(g_cnt[n], 1);
    float v = g_agg2[idx] / c + bias[o];
#pragma unroll
    for (int i = 0; i < C1; i++) v = fmaf(g_h1[n * C1 + i], root[i * C2 + o], v);
    g_h2[idx] = fmaxf(v, 0.f);
}
__global__ void k_node3(const float* __restrict__ root, const float* __restrict__ bias) {
    int idx = blockIdx.x * blockDim.x + threadIdx.x;
    if (idx >= NN * C3) return;
    int n = idx / C3, o = idx % C3;
    float c = (float)max(g_cnt[n], 1);
    float v = g_agg3[idx] / c + bias[o];
#pragma unroll
    for (int i = 0; i < C2; i++) v = fmaf(g_h2[n * C2 + i], root[i * C3 + o], v);
    g_h3[idx] = fmaxf(v, 0.f);
}

// ---------------- CBT: out[i,j] = sum_d |h3[j,d]-h3[i,d]| ----------------
__global__ void k_cbt(float* __restrict__ out) {
    __shared__ float hs[NN * C3];
    int t = threadIdx.x;
    for (int idx = t; idx < NN * C3; idx += blockDim.x) hs[idx] = g_h3[idx];
    __syncthreads();
    int i = blockIdx.x;
    float hi[C3];
#pragma unroll
    for (int d = 0; d < C3; d++) hi[d] = hs[i * C3 + d];
    float s = 0.f;
#pragma unroll
    for (int d = 0; d < C3; d++) s += fabsf(hs[t * C3 + d] - hi[d]);
    out[i * NN + t] = s;
}

extern "C" void kernel_launch(void* const* d_in, const int* in_sizes, int n_in,
                              void* d_out, int out_size) {
    const float* x  = (const float*)d_in[0];
    const float4* ea = (const float4*)d_in[1];
    const void* ei = d_in[2];
    const float* W1 = (const float*)d_in[3];
    const float* b1 = (const float*)d_in[4];
    const float* r1 = (const float*)d_in[5];
    const float* B1 = (const float*)d_in[6];
    const float* W2 = (const float*)d_in[7];
    const float* b2 = (const float*)d_in[8];
    const float* r2 = (const float*)d_in[9];
    const float* B2 = (const float*)d_in[10];
    const float* W3 = (const float*)d_in[11];
    const float* b3 = (const float*)d_in[12];
    const float* r3 = (const float*)d_in[13];
    const float* B3 = (const float*)d_in[14];
    float* out = (float*)d_out;

    int E = in_sizes[2] / 2;
    if (E > EMAX) E = EMAX;

    int eb = (E + 255) / 256;

    k_detect<<<1, 32>>>((const long long*)ei);
    k_convert<<<eb, 256>>>(ei, E);
    k_zero<<<(NN * C1 + 255) / 256, 256>>>();
    k_hist<<<512, 256>>>(E);

    k_edge1<<<eb, 256>>>(x, ea, W1, b1, E);
    k_node1<<<(NN * C1 + 255) / 256, 256>>>(x, r1, B1);

    k_edge2<<<eb, 256>>>(ea, W2, b2, E);
    k_node2<<<(NN * C2 + 255) / 256, 256>>>(r2, B2);

    k_edge3<<<eb, 256>>>(ea, W3, b3, E);
    k_node3<<<(NN * C3 + 255) / 256, 256>>>(r3, B3);

    k_cbt<<<NN, NN>>>(out);
}

// round 7
// speedup vs baseline: 1.5364x; 1.5364x over previous
#include <cuda_runtime.h>

#define NN 512          // nodes
#define C1 36
#define C2 24
#define C3 8
#define EMAX (NN * NN)

typedef unsigned long long u64;

// ---- scratch (device globals; no allocs allowed) ----
__device__ __align__(16) float g_h1[NN * C1];
__device__ __align__(16) float g_h2[NN * C2];
__device__ __align__(16) float g_h3[NN * C3];
__device__ int g_cnt[NN];
__device__ int g_off[NN + 1];
__device__ int g_pos[NN];
__device__ int g_src[EMAX];
__device__ int g_dst[EMAX];
__device__ int g_ssrc[EMAX];            // src in dst-sorted order
__device__ __align__(16) float4 g_ea[EMAX];  // edge_attr in dst-sorted order
__device__ int g_is64;

// ---- f32x2 packed helpers (sm_100a) ----
__device__ __forceinline__ u64 pk(float lo, float hi) {
    u64 r; asm("mov.b64 %0, {%1,%2};" : "=l"(r) : "f"(lo), "f"(hi)); return r;
}
__device__ __forceinline__ void upk(u64 v, float& lo, float& hi) {
    asm("mov.b64 {%0,%1}, %2;" : "=f"(lo), "=f"(hi) : "l"(v));
}
__device__ __forceinline__ u64 fma2(u64 a, u64 b, u64 c) {
    u64 d; asm("fma.rn.f32x2 %0, %1, %2, %3;" : "=l"(d) : "l"(a), "l"(b), "l"(c)); return d;
}
__device__ __forceinline__ u64 d2u(double d) { return __double_as_longlong(d); }

// ---------------- prep: zero counts + dtype detect ----------------
__global__ void k_prep(const long long* __restrict__ ei) {
    __shared__ int bad;
    int t = threadIdx.x;
    if (t == 0) bad = 0;
    g_cnt[t] = 0;
    __syncthreads();
    if (t < 64) {
        long long v = ei[t];
        if (v < 0 || v >= NN) atomicOr(&bad, 1);
    }
    __syncthreads();
    if (t == 0) g_is64 = !bad;
}

// ---------------- convert indices to clean int32, hard-clamped ----------------
__global__ void k_convert(const void* __restrict__ ei, int E) {
    int e = blockIdx.x * blockDim.x + threadIdx.x;
    if (e >= E) return;
    int s, d;
    if (g_is64) {
        const long long* p = (const long long*)ei;
        s = (int)p[e]; d = (int)p[E + e];
    } else {
        const int* p = (const int*)ei;
        s = p[e]; d = p[E + e];
    }
    g_src[e] = s & (NN - 1);
    g_dst[e] = d & (NN - 1);
}

// ---------------- dst histogram ----------------
__global__ void k_hist(int E) {
    __shared__ int s[NN];
    for (int i = threadIdx.x; i < NN; i += blockDim.x) s[i] = 0;
    __syncthreads();
    for (int e = blockIdx.x * blockDim.x + threadIdx.x; e < E; e += gridDim.x * blockDim.x)
        atomicAdd(&s[g_dst[e]], 1);
    __syncthreads();
    for (int i = threadIdx.x; i < NN; i += blockDim.x)
        if (s[i]) atomicAdd(&g_cnt[i], s[i]);
}

// ---------------- exclusive scan over 512 counts (1 block) ----------------
__global__ void k_prefix() {
    __shared__ int s[NN];
    int t = threadIdx.x;
    s[t] = g_cnt[t];
    __syncthreads();
    for (int d = 1; d < NN; d <<= 1) {
        int v = (t >= d) ? s[t - d] : 0;
        __syncthreads();
        s[t] += v;
        __syncthreads();
    }
    g_off[t + 1] = s[t];
    if (t == 0) g_off[0] = 0;
    g_pos[t] = s[t] - g_cnt[t];   // exclusive offset, mutable copy
}

// ---------------- scatter into dst-sorted order ----------------
__global__ void k_scatter(const float4* __restrict__ ea, int E) {
    int e = blockIdx.x * blockDim.x + threadIdx.x;
    if (e >= E) return;
    int d = g_dst[e];
    int p = atomicAdd(&g_pos[d], 1);
    g_ssrc[p] = g_src[e];
    g_ea[p] = ea[e];
}

// ---------------- layer 1 fused: cin=1, cout=36 (scalar; small share of work) ----------------
__global__ __launch_bounds__(256) void k_layer1(
    const float* __restrict__ x, const float* __restrict__ W, const float* __restrict__ b,
    const float* __restrict__ root, const float* __restrict__ bias)
{
    __shared__ float4 Ws[C1];
    __shared__ float bs[C1];
    __shared__ float parts[8][C1];
    __shared__ float xn;
    int n = blockIdx.x, t = threadIdx.x;
    if (t < C1) {
        Ws[t] = make_float4(W[t], W[C1 + t], W[2 * C1 + t], W[3 * C1 + t]);
        bs[t] = b[t];
    }
    if (t == 0) xn = x[n];
    __syncthreads();
    int beg = g_off[n], end = g_off[n + 1];
    float acc[C1];
#pragma unroll
    for (int o = 0; o < C1; o++) acc[o] = 0.f;
    for (int p = beg + t; p < end; p += 256) {
        float4 a = g_ea[p];
        float xs = __ldg(x + g_ssrc[p]);
#pragma unroll
        for (int o = 0; o < C1; o++) {
            float4 w = Ws[o];
            float v = fmaf(a.x, w.x, fmaf(a.y, w.y, fmaf(a.z, w.z, fmaf(a.w, w.w, bs[o]))));
            acc[o] = fmaf(xs, fmaxf(v, 0.f), acc[o]);
        }
    }
#pragma unroll
    for (int o = 0; o < C1; o++)
#pragma unroll
        for (int off = 16; off; off >>= 1)
            acc[o] += __shfl_down_sync(0xffffffffu, acc[o], off);
    int wid = t >> 5, lane = t & 31;
    if (lane == 0)
#pragma unroll
        for (int o = 0; o < C1; o++) parts[wid][o] = acc[o];
    __syncthreads();
    if (t < C1) {
        float s = 0.f;
#pragma unroll
        for (int w = 0; w < 8; w++) s += parts[w][t];
        float cnt = fmaxf((float)(end - beg), 1.f);
        float v = s / cnt + bias[t] + xn * root[t];
        g_h1[n * C1 + t] = fmaxf(v, 0.f);
    }
}

// ---------------- layer 2 fused: cin=36, cout=24, f32x2 packed ----------------
#define P2 (C2 / 2)             // 12 output pairs
#define W2PAIRS (C1 * P2)       // 432
__global__ __launch_bounds__(256) void k_layer2(
    const float* __restrict__ W, const float* __restrict__ b,
    const float* __restrict__ root, const float* __restrict__ bias)
{
    __shared__ double2 WpA[W2PAIRS][2];   // views k=0,1 | k=2,3
    __shared__ u64 WpB[W2PAIRS];          // bias pair
    __shared__ float hprev[C1];
    __shared__ float rootS[C1 * C2];
    __shared__ float parts[8][C2];
    int n = blockIdx.x, t = threadIdx.x;
    for (int idx = t; idx < W2PAIRS; idx += 256) {
        int i = idx / P2, op = idx % P2;
        int c0 = i * C2 + 2 * op;
        WpA[idx][0] = make_double2(
            __longlong_as_double(pk(W[c0], W[c0 + 1])),
            __longlong_as_double(pk(W[864 + c0], W[864 + c0 + 1])));
        WpA[idx][1] = make_double2(
            __longlong_as_double(pk(W[1728 + c0], W[1728 + c0 + 1])),
            __longlong_as_double(pk(W[2592 + c0], W[2592 + c0 + 1])));
        WpB[idx] = pk(b[c0], b[c0 + 1]);
    }
    if (t < C1) hprev[t] = g_h1[n * C1 + t];
    for (int idx = t; idx < C1 * C2; idx += 256) rootS[idx] = root[idx];
    __syncthreads();
    int beg = g_off[n], end = g_off[n + 1];
    u64 acc2[P2];
#pragma unroll
    for (int o = 0; o < P2; o++) acc2[o] = 0ull;
    for (int p = beg + t; p < end; p += 256) {
        float4 a = g_ea[p];
        int src = g_ssrc[p];
        u64 ax = pk(a.x, a.x), ay = pk(a.y, a.y), az = pk(a.z, a.z), aw = pk(a.w, a.w);
        float h[C1];
        const float4* hp = (const float4*)(g_h1 + src * C1);
#pragma unroll
        for (int q = 0; q < C1 / 4; q++) {
            float4 v = __ldg(hp + q);
            h[4 * q] = v.x; h[4 * q + 1] = v.y; h[4 * q + 2] = v.z; h[4 * q + 3] = v.w;
        }
#pragma unroll 4
        for (int i = 0; i < C1; i++) {
            u64 xi2 = pk(h[i], h[i]);
            int base = i * P2;
#pragma unroll
            for (int op = 0; op < P2; op++) {
                double2 d0 = WpA[base + op][0];
                double2 d1 = WpA[base + op][1];
                u64 v = fma2(ax, d2u(d0.x), WpB[base + op]);
                v = fma2(ay, d2u(d0.y), v);
                v = fma2(az, d2u(d1.x), v);
                v = fma2(aw, d2u(d1.y), v);
                float lo, hi; upk(v, lo, hi);
                lo = fmaxf(lo, 0.f); hi = fmaxf(hi, 0.f);
                acc2[op] = fma2(xi2, pk(lo, hi), acc2[op]);
            }
        }
    }
    float acc[C2];
#pragma unroll
    for (int op = 0; op < P2; op++) upk(acc2[op], acc[2 * op], acc[2 * op + 1]);
#pragma unroll
    for (int o = 0; o < C2; o++)
#pragma unroll
        for (int off = 16; off; off >>= 1)
            acc[o] += __shfl_down_sync(0xffffffffu, acc[o], off);
    int wid = t >> 5, lane = t & 31;
    if (lane == 0)
#pragma unroll
        for (int o = 0; o < C2; o++) parts[wid][o] = acc[o];
    __syncthreads();
    if (t < C2) {
        float s = 0.f;
#pragma unroll
        for (int w = 0; w < 8; w++) s += parts[w][t];
        float cnt = fmaxf((float)(end - beg), 1.f);
        float v = s / cnt + bias[t];
#pragma unroll
        for (int i = 0; i < C1; i++) v = fmaf(hprev[i], rootS[i * C2 + t], v);
        g_h2[n * C2 + t] = fmaxf(v, 0.f);
    }
}

// ---------------- layer 3 fused: cin=24, cout=8, f32x2 packed ----------------
#define P3 (C3 / 2)             // 4 output pairs
#define W3PAIRS (C2 * P3)       // 96
__global__ __launch_bounds__(256) void k_layer3(
    const float* __restrict__ W, const float* __restrict__ b,
    const float* __restrict__ root, const float* __restrict__ bias)
{
    __shared__ double2 WpA[W3PAIRS][2];
    __shared__ u64 WpB[W3PAIRS];
    __shared__ float hprev[C2];
    __shared__ float rootS[C2 * C3];
    __shared__ float parts[8][C3];
    int n = blockIdx.x, t = threadIdx.x;
    for (int idx = t; idx < W3PAIRS; idx += 256) {
        int i = idx / P3, op = idx % P3;
        int c0 = i * C3 + 2 * op;
        WpA[idx][0] = make_double2(
            __longlong_as_double(pk(W[c0], W[c0 + 1])),
            __longlong_as_double(pk(W[192 + c0], W[192 + c0 + 1])));
        WpA[idx][1] = make_double2(
            __longlong_as_double(pk(W[384 + c0], W[384 + c0 + 1])),
            __longlong_as_double(pk(W[576 + c0], W[576 + c0 + 1])));
        WpB[idx] = pk(b[c0], b[c0 + 1]);
    }
    if (t < C2) hprev[t] = g_h2[n * C2 + t];
    if (t < C2 * C3) rootS[t] = root[t];
    __syncthreads();
    int beg = g_off[n], end = g_off[n + 1];
    u64 acc2[P3];
#pragma unroll
    for (int o = 0; o < P3; o++) acc2[o] = 0ull;
    for (int p = beg + t; p < end; p += 256) {
        float4 a = g_ea[p];
        int src = g_ssrc[p];
        u64 ax = pk(a.x, a.x), ay = pk(a.y, a.y), az = pk(a.z, a.z), aw = pk(a.w, a.w);
        float h[C2];
        const float4* hp = (const float4*)(g_h2 + src * C2);
#pragma unroll
        for (int q = 0; q < C2 / 4; q++) {
            float4 v = __ldg(hp + q);
            h[4 * q] = v.x; h[4 * q + 1] = v.y; h[4 * q + 2] = v.z; h[4 * q + 3] = v.w;
        }
#pragma unroll 4
        for (int i = 0; i < C2; i++) {
            u64 xi2 = pk(h[i], h[i]);
            int base = i * P3;
#pragma unroll
            for (int op = 0; op < P3; op++) {
                double2 d0 = WpA[base + op][0];
                double2 d1 = WpA[base + op][1];
                u64 v = fma2(ax, d2u(d0.x), WpB[base + op]);
                v = fma2(ay, d2u(d0.y), v);
                v = fma2(az, d2u(d1.x), v);
                v = fma2(aw, d2u(d1.y), v);
                float lo, hi; upk(v, lo, hi);
                lo = fmaxf(lo, 0.f); hi = fmaxf(hi, 0.f);
                acc2[op] = fma2(xi2, pk(lo, hi), acc2[op]);
            }
        }
    }
    float acc[C3];
#pragma unroll
    for (int op = 0; op < P3; op++) upk(acc2[op], acc[2 * op], acc[2 * op + 1]);
#pragma unroll
    for (int o = 0; o < C3; o++)
#pragma unroll
        for (int off = 16; off; off >>= 1)
            acc[o] += __shfl_down_sync(0xffffffffu, acc[o], off);
    int wid = t >> 5, lane = t & 31;
    if (lane == 0)
#pragma unroll
        for (int o = 0; o < C3; o++) parts[wid][o] = acc[o];
    __syncthreads();
    if (t < C3) {
        float s = 0.f;
#pragma unroll
        for (int w = 0; w < 8; w++) s += parts[w][t];
        float cnt = fmaxf((float)(end - beg), 1.f);
        float v = s / cnt + bias[t];
#pragma unroll
        for (int i = 0; i < C2; i++) v = fmaf(hprev[i], rootS[i * C3 + t], v);
        g_h3[n * C3 + t] = fmaxf(v, 0.f);
    }
}

// ---------------- CBT: out[i,j] = sum_d |h3[j,d]-h3[i,d]| ----------------
__global__ void k_cbt(float* __restrict__ out) {
    __shared__ float hs[NN * C3];
    int t = threadIdx.x;
    for (int idx = t; idx < NN * C3; idx += blockDim.x) hs[idx] = g_h3[idx];
    __syncthreads();
    int i = blockIdx.x;
    float hi[C3];
#pragma unroll
    for (int d = 0; d < C3; d++) hi[d] = hs[i * C3 + d];
    float s = 0.f;
#pragma unroll
    for (int d = 0; d < C3; d++) s += fabsf(hs[t * C3 + d] - hi[d]);
    out[i * NN + t] = s;
}

extern "C" void kernel_launch(void* const* d_in, const int* in_sizes, int n_in,
                              void* d_out, int out_size) {
    const float* x  = (const float*)d_in[0];
    const float4* ea = (const float4*)d_in[1];
    const void* ei = d_in[2];
    const float* W1 = (const float*)d_in[3];
    const float* b1 = (const float*)d_in[4];
    const float* r1 = (const float*)d_in[5];
    const float* B1 = (const float*)d_in[6];
    const float* W2 = (const float*)d_in[7];
    const float* b2 = (const float*)d_in[8];
    const float* r2 = (const float*)d_in[9];
    const float* B2 = (const float*)d_in[10];
    const float* W3 = (const float*)d_in[11];
    const float* b3 = (const float*)d_in[12];
    const float* r3 = (const float*)d_in[13];
    const float* B3 = (const float*)d_in[14];
    float* out = (float*)d_out;

    int E = in_sizes[2] / 2;
    if (E > EMAX) E = EMAX;
    int eb = (E + 255) / 256;

    k_prep<<<1, NN>>>((const long long*)ei);
    k_convert<<<eb, 256>>>(ei, E);
    k_hist<<<512, 256>>>(E);
    k_prefix<<<1, NN>>>();
    k_scatter<<<eb, 256>>>(ea, E);

    k_layer1<<<NN, 256>>>(x, W1, b1, r1, B1);
    k_layer2<<<NN, 256>>>(W2, b2, r2, B2);
    k_layer3<<<NN, 256>>>(W3, b3, r3, B3);

    k_cbt<<<NN, NN>>>(out);
}

// round 8
// speedup vs baseline: 1.9208x; 1.2502x over previous
#include <cuda_runtime.h>

#define NN 512          // nodes
#define C1 36
#define C2 24
#define C3 8
#define EMAX (NN * NN)

typedef unsigned long long u64;

// ---- scratch (device globals; no allocs allowed) ----
__device__ __align__(16) float g_h1[NN * C1];
__device__ __align__(16) float g_h2[NN * C2];
__device__ __align__(16) float g_h3[NN * C3];
__device__ int g_cnt[NN];
__device__ int g_off[NN + 1];
__device__ int g_pos[NN];
__device__ int g_ssrc[EMAX];                 // src in dst-sorted order
__device__ __align__(16) float4 g_ea[EMAX];  // edge_attr in dst-sorted order
__device__ int g_is64;

// ---- f32x2 packed helpers (sm_100a) ----
__device__ __forceinline__ u64 pk(float lo, float hi) {
    u64 r; asm("mov.b64 %0, {%1,%2};" : "=l"(r) : "f"(lo), "f"(hi)); return r;
}
__device__ __forceinline__ void upk(u64 v, float& lo, float& hi) {
    asm("mov.b64 {%0,%1}, %2;" : "=f"(lo), "=f"(hi) : "l"(v));
}
__device__ __forceinline__ u64 fma2(u64 a, u64 b, u64 c) {
    u64 d; asm("fma.rn.f32x2 %0, %1, %2, %3;" : "=l"(d) : "l"(a), "l"(b), "l"(c)); return d;
}
__device__ __forceinline__ u64 relu2(u64 v) {
    u64 r;
    asm("{\n\t.reg .f32 lo, hi;\n\t"
        "mov.b64 {lo, hi}, %1;\n\t"
        "max.f32 lo, lo, 0f00000000;\n\t"
        "max.f32 hi, hi, 0f00000000;\n\t"
        "mov.b64 %0, {lo, hi};\n\t}"
        : "=l"(r) : "l"(v));
    return r;
}
__device__ __forceinline__ u64 d2u(double d) { return __double_as_longlong(d); }

// ---- edge index fetch (dtype-robust) ----
__device__ __forceinline__ int eidx(const void* ei, int is64, int pos) {
    int v = is64 ? (int)((const long long*)ei)[pos] : ((const int*)ei)[pos];
    return v & (NN - 1);
}

// ---------------- prep: zero counts + dtype detect ----------------
__global__ void k_prep(const long long* __restrict__ ei) {
    __shared__ int bad;
    int t = threadIdx.x;
    if (t == 0) bad = 0;
    g_cnt[t] = 0;
    __syncthreads();
    if (t < 64) {
        long long v = ei[t];
        if (v < 0 || v >= NN) atomicOr(&bad, 1);
    }
    __syncthreads();
    if (t == 0) g_is64 = !bad;
}

// ---------------- dst histogram (reads ei directly) ----------------
__global__ void k_hist(const void* __restrict__ ei, int E) {
    __shared__ int s[NN];
    int is64 = g_is64;
    for (int i = threadIdx.x; i < NN; i += blockDim.x) s[i] = 0;
    __syncthreads();
    for (int e = blockIdx.x * blockDim.x + threadIdx.x; e < E; e += gridDim.x * blockDim.x)
        atomicAdd(&s[eidx(ei, is64, E + e)], 1);
    __syncthreads();
    for (int i = threadIdx.x; i < NN; i += blockDim.x)
        if (s[i]) atomicAdd(&g_cnt[i], s[i]);
}

// ---------------- exclusive scan over 512 counts (1 block) ----------------
__global__ void k_prefix() {
    __shared__ int s[NN];
    int t = threadIdx.x;
    s[t] = g_cnt[t];
    __syncthreads();
    for (int d = 1; d < NN; d <<= 1) {
        int v = (t >= d) ? s[t - d] : 0;
        __syncthreads();
        s[t] += v;
        __syncthreads();
    }
    g_off[t + 1] = s[t];
    if (t == 0) g_off[0] = 0;
    g_pos[t] = s[t] - g_cnt[t];   // exclusive offset, mutable copy
}

// ---------------- scatter into dst-sorted order (reads ei directly) ----------------
__global__ void k_scatter(const void* __restrict__ ei, const float4* __restrict__ ea, int E) {
    int e = blockIdx.x * blockDim.x + threadIdx.x;
    if (e >= E) return;
    int is64 = g_is64;
    int s = eidx(ei, is64, e);
    int d = eidx(ei, is64, E + e);
    int p = atomicAdd(&g_pos[d], 1);
    g_ssrc[p] = s;
    g_ea[p] = ea[e];
}

// ---------------- layer 1 fused: cin=1, cout=36, packed, 2-edge ----------------
#define P1 (C1 / 2)             // 18 output pairs
__global__ __launch_bounds__(256) void k_layer1(
    const float* __restrict__ x, const float* __restrict__ W, const float* __restrict__ b,
    const float* __restrict__ root, const float* __restrict__ bias)
{
    __shared__ double2 Wp[P1][2];    // k=0,1 | k=2,3 views, packed over (o,o+1)
    __shared__ u64 Bp[P1];
    __shared__ float parts[8][C1];
    __shared__ float xn;
    int n = blockIdx.x, t = threadIdx.x;
    if (t < P1) {
        int c0 = 2 * t;
        Wp[t][0] = make_double2(
            __longlong_as_double(pk(W[c0], W[c0 + 1])),
            __longlong_as_double(pk(W[C1 + c0], W[C1 + c0 + 1])));
        Wp[t][1] = make_double2(
            __longlong_as_double(pk(W[2 * C1 + c0], W[2 * C1 + c0 + 1])),
            __longlong_as_double(pk(W[3 * C1 + c0], W[3 * C1 + c0 + 1])));
        Bp[t] = pk(b[c0], b[c0 + 1]);
    }
    if (t == 0) xn = x[n];
    __syncthreads();
    int beg = g_off[n], end = g_off[n + 1];
    u64 acc2[P1];
#pragma unroll
    for (int o = 0; o < P1; o++) acc2[o] = 0ull;
    for (int p = beg + t; p < end; p += 512) {
        int p2 = p + 256;
        bool has2 = p2 < end;
        float4 aA = g_ea[p];
        float4 aB = has2 ? g_ea[p2] : make_float4(0.f, 0.f, 0.f, 0.f);
        float xsA = __ldg(x + g_ssrc[p]);
        float xsB = has2 ? __ldg(x + g_ssrc[p2]) : 0.f;
        u64 axA = pk(aA.x, aA.x), ayA = pk(aA.y, aA.y), azA = pk(aA.z, aA.z), awA = pk(aA.w, aA.w);
        u64 axB = pk(aB.x, aB.x), ayB = pk(aB.y, aB.y), azB = pk(aB.z, aB.z), awB = pk(aB.w, aB.w);
        u64 xiA = pk(xsA, xsA), xiB = pk(xsB, xsB);
#pragma unroll
        for (int op = 0; op < P1; op++) {
            double2 d0 = Wp[op][0];
            double2 d1 = Wp[op][1];
            u64 vA = fma2(axA, d2u(d0.x), Bp[op]);
            vA = fma2(ayA, d2u(d0.y), vA);
            vA = fma2(azA, d2u(d1.x), vA);
            vA = fma2(awA, d2u(d1.y), vA);
            acc2[op] = fma2(xiA, relu2(vA), acc2[op]);
            u64 vB = fma2(axB, d2u(d0.x), Bp[op]);
            vB = fma2(ayB, d2u(d0.y), vB);
            vB = fma2(azB, d2u(d1.x), vB);
            vB = fma2(awB, d2u(d1.y), vB);
            acc2[op] = fma2(xiB, relu2(vB), acc2[op]);
        }
    }
    float acc[C1];
#pragma unroll
    for (int op = 0; op < P1; op++) upk(acc2[op], acc[2 * op], acc[2 * op + 1]);
#pragma unroll
    for (int o = 0; o < C1; o++)
#pragma unroll
        for (int off = 16; off; off >>= 1)
            acc[o] += __shfl_down_sync(0xffffffffu, acc[o], off);
    int wid = t >> 5, lane = t & 31;
    if (lane == 0)
#pragma unroll
        for (int o = 0; o < C1; o++) parts[wid][o] = acc[o];
    __syncthreads();
    if (t < C1) {
        float s = 0.f;
#pragma unroll
        for (int w = 0; w < 8; w++) s += parts[w][t];
        float cnt = fmaxf((float)(end - beg), 1.f);
        float v = s / cnt + bias[t] + xn * root[t];
        g_h1[n * C1 + t] = fmaxf(v, 0.f);
    }
}

// ---------------- layer 2 fused: cin=36, cout=24, packed, 2-edge ----------------
#define P2 (C2 / 2)             // 12 output pairs
#define W2PAIRS (C1 * P2)       // 432
__global__ __launch_bounds__(256) void k_layer2(
    const float* __restrict__ W, const float* __restrict__ b,
    const float* __restrict__ root, const float* __restrict__ bias)
{
    __shared__ double2 WpA[W2PAIRS][2];   // views k=0,1 | k=2,3
    __shared__ u64 WpB[W2PAIRS];          // bias pair
    __shared__ float hprev[C1];
    __shared__ float rootS[C1 * C2];
    __shared__ float parts[8][C2];
    int n = blockIdx.x, t = threadIdx.x;
    for (int idx = t; idx < W2PAIRS; idx += 256) {
        int i = idx / P2, op = idx % P2;
        int c0 = i * C2 + 2 * op;
        WpA[idx][0] = make_double2(
            __longlong_as_double(pk(W[c0], W[c0 + 1])),
            __longlong_as_double(pk(W[864 + c0], W[864 + c0 + 1])));
        WpA[idx][1] = make_double2(
            __longlong_as_double(pk(W[1728 + c0], W[1728 + c0 + 1])),
            __longlong_as_double(pk(W[2592 + c0], W[2592 + c0 + 1])));
        WpB[idx] = pk(b[c0], b[c0 + 1]);
    }
    if (t < C1) hprev[t] = g_h1[n * C1 + t];
    for (int idx = t; idx < C1 * C2; idx += 256) rootS[idx] = root[idx];
    __syncthreads();
    int beg = g_off[n], end = g_off[n + 1];
    u64 acc2[P2];
#pragma unroll
    for (int o = 0; o < P2; o++) acc2[o] = 0ull;
    for (int p = beg + t; p < end; p += 512) {
        int p2 = p + 256;
        bool has2 = p2 < end;
        float4 aA = g_ea[p];
        float4 aB = has2 ? g_ea[p2] : make_float4(0.f, 0.f, 0.f, 0.f);
        int srcA = g_ssrc[p];
        int srcB = has2 ? g_ssrc[p2] : 0;
        u64 axA = pk(aA.x, aA.x), ayA = pk(aA.y, aA.y), azA = pk(aA.z, aA.z), awA = pk(aA.w, aA.w);
        u64 axB = pk(aB.x, aB.x), ayB = pk(aB.y, aB.y), azB = pk(aB.z, aB.z), awB = pk(aB.w, aB.w);
        float hA[C1], hB[C1];
        const float4* hpA = (const float4*)(g_h1 + srcA * C1);
        const float4* hpB = (const float4*)(g_h1 + srcB * C1);
#pragma unroll
        for (int q = 0; q < C1 / 4; q++) {
            float4 v = __ldg(hpA + q);
            hA[4 * q] = v.x; hA[4 * q + 1] = v.y; hA[4 * q + 2] = v.z; hA[4 * q + 3] = v.w;
        }
#pragma unroll
        for (int q = 0; q < C1 / 4; q++) {
            float4 v = __ldg(hpB + q);
            float m = has2 ? 1.f : 0.f;
            hB[4 * q] = v.x * m; hB[4 * q + 1] = v.y * m; hB[4 * q + 2] = v.z * m; hB[4 * q + 3] = v.w * m;
        }
#pragma unroll 4
        for (int i = 0; i < C1; i++) {
            u64 xiA = pk(hA[i], hA[i]);
            u64 xiB = pk(hB[i], hB[i]);
            int base = i * P2;
#pragma unroll
            for (int op = 0; op < P2; op++) {
                double2 d0 = WpA[base + op][0];
                double2 d1 = WpA[base + op][1];
                u64 vA = fma2(axA, d2u(d0.x), WpB[base + op]);
                vA = fma2(ayA, d2u(d0.y), vA);
                vA = fma2(azA, d2u(d1.x), vA);
                vA = fma2(awA, d2u(d1.y), vA);
                acc2[op] = fma2(xiA, relu2(vA), acc2[op]);
                u64 vB = fma2(axB, d2u(d0.x), WpB[base + op]);
                vB = fma2(ayB, d2u(d0.y), vB);
                vB = fma2(azB, d2u(d1.x), vB);
                vB = fma2(awB, d2u(d1.y), vB);
                acc2[op] = fma2(xiB, relu2(vB), acc2[op]);
            }
        }
    }
    float acc[C2];
#pragma unroll
    for (int op = 0; op < P2; op++) upk(acc2[op], acc[2 * op], acc[2 * op + 1]);
#pragma unroll
    for (int o = 0; o < C2; o++)
#pragma unroll
        for (int off = 16; off; off >>= 1)
            acc[o] += __shfl_down_sync(0xffffffffu, acc[o], off);
    int wid = t >> 5, lane = t & 31;
    if (lane == 0)
#pragma unroll
        for (int o = 0; o < C2; o++) parts[wid][o] = acc[o];
    __syncthreads();
    if (t < C2) {
        float s = 0.f;
#pragma unroll
        for (int w = 0; w < 8; w++) s += parts[w][t];
        float cnt = fmaxf((float)(end - beg), 1.f);
        float v = s / cnt + bias[t];
#pragma unroll
        for (int i = 0; i < C1; i++) v = fmaf(hprev[i], rootS[i * C2 + t], v);
        g_h2[n * C2 + t] = fmaxf(v, 0.f);
    }
}

// ---------------- layer 3 fused: cin=24, cout=8, packed, 2-edge ----------------
#define P3 (C3 / 2)             // 4 output pairs
#define W3PAIRS (C2 * P3)       // 96
__global__ __launch_bounds__(256) void k_layer3(
    const float* __restrict__ W, const float* __restrict__ b,
    const float* __restrict__ root, const float* __restrict__ bias)
{
    __shared__ double2 WpA[W3PAIRS][2];
    __shared__ u64 WpB[W3PAIRS];
    __shared__ float hprev[C2];
    __shared__ float rootS[C2 * C3];
    __shared__ float parts[8][C3];
    int n = blockIdx.x, t = threadIdx.x;
    for (int idx = t; idx < W3PAIRS; idx += 256) {
        int i = idx / P3, op = idx % P3;
        int c0 = i * C3 + 2 * op;
        WpA[idx][0] = make_double2(
            __longlong_as_double(pk(W[c0], W[c0 + 1])),
            __longlong_as_double(pk(W[192 + c0], W[192 + c0 + 1])));
        WpA[idx][1] = make_double2(
            __longlong_as_double(pk(W[384 + c0], W[384 + c0 + 1])),
            __longlong_as_double(pk(W[576 + c0], W[576 + c0 + 1])));
        WpB[idx] = pk(b[c0], b[c0 + 1]);
    }
    if (t < C2) hprev[t] = g_h2[n * C2 + t];
    if (t < C2 * C3) rootS[t] = root[t];
    __syncthreads();
    int beg = g_off[n], end = g_off[n + 1];
    u64 acc2[P3];
#pragma unroll
    for (int o = 0; o < P3; o++) acc2[o] = 0ull;
    for (int p = beg + t; p < end; p += 512) {
        int p2 = p + 256;
        bool has2 = p2 < end;
        float4 aA = g_ea[p];
        float4 aB = has2 ? g_ea[p2] : make_float4(0.f, 0.f, 0.f, 0.f);
        int srcA = g_ssrc[p];
        int srcB = has2 ? g_ssrc[p2] : 0;
        u64 axA = pk(aA.x, aA.x), ayA = pk(aA.y, aA.y), azA = pk(aA.z, aA.z), awA = pk(aA.w, aA.w);
        u64 axB = pk(aB.x, aB.x), ayB = pk(aB.y, aB.y), azB = pk(aB.z, aB.z), awB = pk(aB.w, aB.w);
        float hA[C2], hB[C2];
        const float4* hpA = (const float4*)(g_h2 + srcA * C2);
        const float4* hpB = (const float4*)(g_h2 + srcB * C2);
#pragma unroll
        for (int q = 0; q < C2 / 4; q++) {
            float4 v = __ldg(hpA + q);
            hA[4 * q] = v.x; hA[4 * q + 1] = v.y; hA[4 * q + 2] = v.z; hA[4 * q + 3] = v.w;
        }
#pragma unroll
        for (int q = 0; q < C2 / 4; q++) {
            float4 v = __ldg(hpB + q);
            float m = has2 ? 1.f : 0.f;
            hB[4 * q] = v.x * m; hB[4 * q + 1] = v.y * m; hB[4 * q + 2] = v.z * m; hB[4 * q + 3] = v.w * m;
        }
#pragma unroll 4
        for (int i = 0; i < C2; i++) {
            u64 xiA = pk(hA[i], hA[i]);
            u64 xiB = pk(hB[i], hB[i]);
            int base = i * P3;
#pragma unroll
            for (int op = 0; op < P3; op++) {
                double2 d0 = WpA[base + op][0];
                double2 d1 = WpA[base + op][1];
                u64 vA = fma2(axA, d2u(d0.x), WpB[base + op]);
                vA = fma2(ayA, d2u(d0.y), vA);
                vA = fma2(azA, d2u(d1.x), vA);
                vA = fma2(awA, d2u(d1.y), vA);
                acc2[op] = fma2(xiA, relu2(vA), acc2[op]);
                u64 vB = fma2(axB, d2u(d0.x), WpB[base + op]);
                vB = fma2(ayB, d2u(d0.y), vB);
                vB = fma2(azB, d2u(d1.x), vB);
                vB = fma2(awB, d2u(d1.y), vB);
                acc2[op] = fma2(xiB, relu2(vB), acc2[op]);
            }
        }
    }
    float acc[C3];
#pragma unroll
    for (int op = 0; op < P3; op++) upk(acc2[op], acc[2 * op], acc[2 * op + 1]);
#pragma unroll
    for (int o = 0; o < C3; o++)
#pragma unroll
        for (int off = 16; off; off >>= 1)
            acc[o] += __shfl_down_sync(0xffffffffu, acc[o], off);
    int wid = t >> 5, lane = t & 31;
    if (lane == 0)
#pragma unroll
        for (int o = 0; o < C3; o++) parts[wid][o] = acc[o];
    __syncthreads();
    if (t < C3) {
        float s = 0.f;
#pragma unroll
        for (int w = 0; w < 8; w++) s += parts[w][t];
        float cnt = fmaxf((float)(end - beg), 1.f);
        float v = s / cnt + bias[t];
#pragma unroll
        for (int i = 0; i < C2; i++) v = fmaf(hprev[i], rootS[i * C3 + t], v);
        g_h3[n * C3 + t] = fmaxf(v, 0.f);
    }
}

// ---------------- CBT: out[i,j] = sum_d |h3[j,d]-h3[i,d]| ----------------
__global__ void k_cbt(float* __restrict__ out) {
    __shared__ float hs[NN * C3];
    int t = threadIdx.x;
    for (int idx = t; idx < NN * C3; idx += blockDim.x) hs[idx] = g_h3[idx];
    __syncthreads();
    int i = blockIdx.x;
    float hi[C3];
#pragma unroll
    for (int d = 0; d < C3; d++) hi[d] = hs[i * C3 + d];
    float s = 0.f;
#pragma unroll
    for (int d = 0; d < C3; d++) s += fabsf(hs[t * C3 + d] - hi[d]);
    out[i * NN + t] = s;
}

extern "C" void kernel_launch(void* const* d_in, const int* in_sizes, int n_in,
                              void* d_out, int out_size) {
    const float* x  = (const float*)d_in[0];
    const float4* ea = (const float4*)d_in[1];
    const void* ei = d_in[2];
    const float* W1 = (const float*)d_in[3];
    const float* b1 = (const float*)d_in[4];
    const float* r1 = (const float*)d_in[5];
    const float* B1 = (const float*)d_in[6];
    const float* W2 = (const float*)d_in[7];
    const float* b2 = (const float*)d_in[8];
    const float* r2 = (const float*)d_in[9];
    const float* B2 = (const float*)d_in[10];
    const float* W3 = (const float*)d_in[11];
    const float* b3 = (const float*)d_in[12];
    const float* r3 = (const float*)d_in[13];
    const float* B3 = (const float*)d_in[14];
    float* out = (float*)d_out;

    int E = in_sizes[2] / 2;
    if (E > EMAX) E = EMAX;
    int eb = (E + 255) / 256;

    k_prep<<<1, NN>>>((const long long*)ei);
    k_hist<<<512, 256>>>(ei, E);
    k_prefix<<<1, NN>>>();
    k_scatter<<<eb, 256>>>(ei, ea, E);

    k_layer1<<<NN, 256>>>(x, W1, b1, r1, B1);
    k_layer2<<<NN, 256>>>(W2, b2, r2, B2);
    k_layer3<<<NN, 256>>>(W3, b3, r3, B3);

    k_cbt<<<NN, NN>>>(out);
}